// round 2
// baseline (speedup 1.0000x reference)
#include <cuda_runtime.h>

#define NTOK 262144
#define NSEG 4096
#define DDIM 256
#define ADIM 128
#define NB   256      // scan blocks: NTOK / 1024
#define BUF  2048     // smem logit buffer per segment (spill beyond)

// ---------------- scratch (no allocations allowed) ----------------
__device__ int                d_ends[NSEG];
__device__ unsigned long long d_desc[NB];     // decoupled-lookback descriptors
__device__ float              d_Mt[DDIM * DDIM];
__device__ float              d_V[NSEG * DDIM];
__device__ float              d_spill[NTOK];  // logits spill for segments > BUF

// ---------------- init (reset lookback flags each replay) ----------------
__global__ void initK() {
    int t = threadIdx.x;
    if (t < NB) d_desc[t] = 0ull;
}

// ---------------- single-pass scan of `queries` -> ends[] ----------------
// desc: [33:32]=status (0 invalid, 1 aggregate, 2 prefix), [31:0]=value
__global__ void scanF(const int* __restrict__ q) {
    __shared__ int warpOff[8];
    __shared__ int warpSums[8];
    __shared__ int blockAgg;
    __shared__ int blockPrefix;

    int t = threadIdx.x, b = blockIdx.x;
    int lane = t & 31, wid = t >> 5;

    int4 v = ((const int4*)q)[b * 256 + t];
    int s = v.x + v.y + v.z + v.w;

    // warp inclusive scan
    int inc = s;
#pragma unroll
    for (int off = 1; off < 32; off <<= 1) {
        int n = __shfl_up_sync(0xffffffffu, inc, off);
        if (lane >= off) inc += n;
    }
    if (lane == 31) warpSums[wid] = inc;
    __syncthreads();

    if (wid == 0 && lane < 8) {
        int w  = warpSums[lane];
        int wi = w;
#pragma unroll
        for (int off = 1; off < 8; off <<= 1) {
            int n = __shfl_up_sync(0xffu, wi, off);
            if (lane >= off) wi += n;
        }
        warpOff[lane] = wi - w;
        if (lane == 7) {
            blockAgg = wi;
            unsigned long long pub = ((b == 0) ? (2ull << 32) : (1ull << 32))
                                     | (unsigned)wi;
            atomicExch(&d_desc[b], pub);   // publish aggregate (or prefix for b0)
            if (b == 0) blockPrefix = 0;
        }
    }
    __syncthreads();

    // warp-parallel lookback (warp 0)
    if (b > 0 && wid == 0) {
        long long run = 0;
        int offbase = 1;
        while (true) {
            int idx = b - (offbase + lane);
            int st; unsigned val;
            if (idx >= 0) {
                unsigned long long d =
                    *((volatile const unsigned long long*)(d_desc + idx));
                st = (int)(d >> 32); val = (unsigned)d;
            } else { st = 2; val = 0; }   // virtual prefix=0 past block 0
            unsigned ready = __ballot_sync(0xffffffffu, st != 0);
            if (ready != 0xffffffffu) continue;
            unsigned pm = __ballot_sync(0xffffffffu, st == 2);
            unsigned contrib;
            if (pm) {
                int nearest = __ffs(pm) - 1;       // closest predecessor w/ prefix
                contrib = (lane <= nearest) ? val : 0u;
            } else {
                contrib = val;
            }
#pragma unroll
            for (int o = 16; o > 0; o >>= 1)
                contrib += __shfl_down_sync(0xffffffffu, contrib, o);
            contrib = __shfl_sync(0xffffffffu, contrib, 0);
            run += contrib;
            if (pm) break;
            offbase += 32;
        }
        if (lane == 0) {
            blockPrefix = (int)run;
            atomicExch(&d_desc[b],
                       (2ull << 32) | (unsigned)((int)run + blockAgg));
        }
    }
    __syncthreads();

    // scatter end positions
    int p  = blockPrefix + warpOff[wid] + inc - s;
    int g0 = (b * 256 + t) * 4;
    if (v.x) d_ends[p++] = g0 + 0;
    if (v.y) d_ends[p++] = g0 + 1;
    if (v.z) d_ends[p++] = g0 + 2;
    if (v.w) d_ends[p++] = g0 + 3;
}

// ---------------- Mt[k][n] = sum_a Wq[a][k] * Wk[a][n] ----------------
__global__ void mtK(const float* __restrict__ Wq, const float* __restrict__ Wk) {
    int k = blockIdx.x;
    int n = threadIdx.x;
    float acc = 0.0f;
#pragma unroll 8
    for (int a = 0; a < ADIM; a++)
        acc += __ldg(Wq + a * DDIM + k) * __ldg(Wk + a * DDIM + n);
    d_Mt[k * DDIM + n] = acc;
}

// ---------------- V = gather(X, ends) @ Mt  (4096x256 @ 256x256) ----------------
__global__ void gemmV(const float* __restrict__ X) {
    __shared__ float As[64][33];
    __shared__ __align__(16) float Bs[32][64];
    __shared__ int endsS[64];

    int t  = threadIdx.x;
    int rb = blockIdx.y;
    int nb = blockIdx.x;
    if (t < 64) endsS[t] = d_ends[rb * 64 + t];
    __syncthreads();

    int tx = t & 15;
    int ty = t >> 4;
    float acc[4][4];
#pragma unroll
    for (int i = 0; i < 4; i++)
#pragma unroll
        for (int j = 0; j < 4; j++) acc[i][j] = 0.0f;

    for (int kt = 0; kt < 8; kt++) {
#pragma unroll
        for (int l = 0; l < 2; l++) {
            int f   = t + l * 256;
            int row = f >> 3;
            int k4  = f & 7;
            float4 x = __ldg((const float4*)(X + (size_t)endsS[row] * DDIM + kt * 32) + k4);
            As[row][k4 * 4 + 0] = x.x;
            As[row][k4 * 4 + 1] = x.y;
            As[row][k4 * 4 + 2] = x.z;
            As[row][k4 * 4 + 3] = x.w;
        }
#pragma unroll
        for (int l = 0; l < 2; l++) {
            int f  = t + l * 256;
            int kk = f >> 4;
            int n4 = f & 15;
            float4 bv = __ldg((const float4*)(d_Mt + (kt * 32 + kk) * DDIM + nb * 64) + n4);
            *(float4*)&Bs[kk][n4 * 4] = bv;
        }
        __syncthreads();
#pragma unroll
        for (int kk = 0; kk < 32; kk++) {
            float a0 = As[ty * 4 + 0][kk];
            float a1 = As[ty * 4 + 1][kk];
            float a2 = As[ty * 4 + 2][kk];
            float a3 = As[ty * 4 + 3][kk];
            float4 bv = *(const float4*)&Bs[kk][tx * 4];
            acc[0][0] += a0 * bv.x; acc[0][1] += a0 * bv.y; acc[0][2] += a0 * bv.z; acc[0][3] += a0 * bv.w;
            acc[1][0] += a1 * bv.x; acc[1][1] += a1 * bv.y; acc[1][2] += a1 * bv.z; acc[1][3] += a1 * bv.w;
            acc[2][0] += a2 * bv.x; acc[2][1] += a2 * bv.y; acc[2][2] += a2 * bv.z; acc[2][3] += a2 * bv.w;
            acc[3][0] += a3 * bv.x; acc[3][1] += a3 * bv.y; acc[3][2] += a3 * bv.z; acc[3][3] += a3 * bv.w;
        }
        __syncthreads();
    }
#pragma unroll
    for (int i = 0; i < 4; i++) {
        float4 o = make_float4(acc[i][0], acc[i][1], acc[i][2], acc[i][3]);
        *(float4*)(d_V + (size_t)(rb * 64 + ty * 4 + i) * DDIM + nb * 64 + tx * 4) = o;
    }
}

// ---------------- fused logits + segmented softmax (block per segment) ----------------
__global__ void fusedK(const float* __restrict__ X, float* __restrict__ out) {
    __shared__ float sl[BUF];
    __shared__ float wm[8], ws[8];
    __shared__ float bm, binvS;
    __shared__ int sStart, sLen;

    int b = blockIdx.x, t = threadIdx.x;
    int lane = t & 31, wid = t >> 5;

    if (t == 0) {
        int e  = d_ends[b];
        int st = (b == 0) ? 0 : (d_ends[b - 1] + 1);
        sStart = st; sLen = e - st + 1;
    }
    __syncthreads();
    int start = sStart, len = sLen;

    // this segment's v (registers, reused for every token)
    const float4* vr = (const float4*)(d_V + (size_t)b * DDIM);
    float4 v0 = __ldg(vr + lane);
    float4 v1 = __ldg(vr + lane + 32);

    float m = -INFINITY, ssum = 0.0f;
    for (int i = wid; i < len; i += 8) {
        const float4* xr = (const float4*)(X + (size_t)(start + i) * DDIM);
        float4 a = __ldcs(xr + lane);
        float4 c = __ldcs(xr + lane + 32);
        float p = a.x * v0.x + a.y * v0.y + a.z * v0.z + a.w * v0.w
                + c.x * v1.x + c.y * v1.y + c.z * v1.z + c.w * v1.w;
#pragma unroll
        for (int o = 16; o > 0; o >>= 1)
            p += __shfl_down_sync(0xffffffffu, p, o);
        if (lane == 0) {
            if (i < BUF) sl[i] = p; else d_spill[start + i] = p;
            float mn = fmaxf(m, p);
            ssum = ssum * __expf(m - mn) + __expf(p - mn);
            m = mn;
        }
    }
    if (lane == 0) { wm[wid] = m; ws[wid] = ssum; }
    __syncthreads();
    if (t == 0) {
        float M = -INFINITY;
#pragma unroll
        for (int w = 0; w < 8; w++) M = fmaxf(M, wm[w]);
        float S = 0.0f;
#pragma unroll
        for (int w = 0; w < 8; w++) S += ws[w] * __expf(wm[w] - M);
        bm = M; binvS = 1.0f / S;
    }
    __syncthreads();
    float M = bm, invS = binvS;
    for (int i = t; i < len; i += 256) {
        float l = (i < BUF) ? sl[i] : d_spill[start + i];
        out[start + i] = __expf(l - M) * invS;
    }
}

extern "C" void kernel_launch(void* const* d_in, const int* in_sizes, int n_in,
                              void* d_out, int out_size) {
    const float* X  = (const float*)d_in[0];
    const int*   q  = (const int*)d_in[1];
    const float* Wq = (const float*)d_in[3];
    const float* Wk = (const float*)d_in[4];
    float* out = (float*)d_out;

    initK<<<1, 256>>>();
    scanF<<<NB, 256>>>(q);
    mtK<<<DDIM, DDIM>>>(Wq, Wk);
    gemmV<<<dim3(DDIM / 64, NSEG / 64), 256>>>(X);
    fusedK<<<NSEG, 256>>>(X, out);
}

// round 5
// speedup vs baseline: 1.0926x; 1.0926x over previous
#include <cuda_runtime.h>

#define NTOK 262144
#define NSEG 4096
#define DDIM 256
#define ADIM 128
#define NB   256      // scan blocks: NTOK / 1024

// ---------------- scratch (no allocations allowed) ----------------
__device__ int                d_seg[NTOK];
__device__ int                d_ends[NSEG];
__device__ unsigned long long d_desc[NB];     // decoupled-lookback descriptors
__device__ float              d_Mt[DDIM * DDIM];
__device__ float              d_V[NSEG * DDIM];
__device__ float              d_logits[NTOK];

// ---------------- init (reset lookback flags each replay) ----------------
__global__ void initK() {
    int t = threadIdx.x;
    if (t < NB) d_desc[t] = 0ull;
}

// ---------------- single-pass scan of `queries` -> seg[] + ends[] ----------------
// desc: [33:32]=status (0 invalid, 1 aggregate, 2 prefix), [31:0]=value
__global__ void scanF(const int* __restrict__ q) {
    __shared__ int warpOff[8];
    __shared__ int warpSums[8];
    __shared__ int blockAgg;
    __shared__ int blockPrefix;

    int t = threadIdx.x, b = blockIdx.x;
    int lane = t & 31, wid = t >> 5;

    int4 v = ((const int4*)q)[b * 256 + t];
    int s = v.x + v.y + v.z + v.w;

    int inc = s;
#pragma unroll
    for (int off = 1; off < 32; off <<= 1) {
        int n = __shfl_up_sync(0xffffffffu, inc, off);
        if (lane >= off) inc += n;
    }
    if (lane == 31) warpSums[wid] = inc;
    __syncthreads();

    if (wid == 0 && lane < 8) {
        int w  = warpSums[lane];
        int wi = w;
#pragma unroll
        for (int off = 1; off < 8; off <<= 1) {
            int n = __shfl_up_sync(0xffu, wi, off);
            if (lane >= off) wi += n;
        }
        warpOff[lane] = wi - w;
        if (lane == 7) {
            blockAgg = wi;
            unsigned long long pub = ((b == 0) ? (2ull << 32) : (1ull << 32))
                                     | (unsigned)wi;
            atomicExch(&d_desc[b], pub);
            if (b == 0) blockPrefix = 0;
        }
    }
    __syncthreads();

    if (b > 0 && wid == 0) {
        long long run = 0;
        int offbase = 1;
        while (true) {
            int idx = b - (offbase + lane);
            int st; unsigned val;
            if (idx >= 0) {
                unsigned long long d =
                    *((volatile const unsigned long long*)(d_desc + idx));
                st = (int)(d >> 32); val = (unsigned)d;
            } else { st = 2; val = 0; }
            unsigned ready = __ballot_sync(0xffffffffu, st != 0);
            if (ready != 0xffffffffu) continue;
            unsigned pm = __ballot_sync(0xffffffffu, st == 2);
            unsigned contrib;
            if (pm) {
                int nearest = __ffs(pm) - 1;
                contrib = (lane <= nearest) ? val : 0u;
            } else {
                contrib = val;
            }
#pragma unroll
            for (int o = 16; o > 0; o >>= 1)
                contrib += __shfl_down_sync(0xffffffffu, contrib, o);
            contrib = __shfl_sync(0xffffffffu, contrib, 0);
            run += contrib;
            if (pm) break;
            offbase += 32;
        }
        if (lane == 0) {
            blockPrefix = (int)run;
            atomicExch(&d_desc[b],
                       (2ull << 32) | (unsigned)((int)run + blockAgg));
        }
    }
    __syncthreads();

    // exclusive prefix at this int4 = segment id of first element
    int p  = blockPrefix + warpOff[wid] + inc - s;
    int g0 = (b * 256 + t) * 4;
    int4 sv;
    sv.x = p; if (v.x) { d_ends[p] = g0 + 0; p++; }
    sv.y = p; if (v.y) { d_ends[p] = g0 + 1; p++; }
    sv.z = p; if (v.z) { d_ends[p] = g0 + 2; p++; }
    sv.w = p; if (v.w) { d_ends[p] = g0 + 3; p++; }
    ((int4*)d_seg)[b * 256 + t] = sv;
}

// ---------------- Mt[k][n] = sum_a Wq[a][k] * Wk[a][n] ----------------
__global__ void mtK(const float* __restrict__ Wq, const float* __restrict__ Wk) {
    int k = blockIdx.x;
    int n = threadIdx.x;
    float acc = 0.0f;
#pragma unroll 8
    for (int a = 0; a < ADIM; a++)
        acc += __ldg(Wq + a * DDIM + k) * __ldg(Wk + a * DDIM + n);
    d_Mt[k * DDIM + n] = acc;
}

// ---------------- V = gather(X, ends) @ Mt ----------------
// BM=32, BN=64, BK=32; 256 threads; 2x4 micro-tile; grid 512 blocks.
__global__ void gemmV(const float* __restrict__ X) {
    __shared__ float As[32][33];
    __shared__ __align__(16) float Bs[32][64];
    __shared__ int endsS[32];

    int t  = threadIdx.x;
    int rb = blockIdx.y;     // 0..127 (32 segments each)
    int nb = blockIdx.x;     // 0..3   (64 cols each)
    if (t < 32) endsS[t] = d_ends[rb * 32 + t];
    __syncthreads();

    int tx = t & 15;         // n: 16 x 4
    int ty = t >> 4;         // m: 16 x 2
    float acc[2][4] = {};

    for (int kt = 0; kt < 8; kt++) {
        {   // A tile: 32 rows x 32 k = 256 float4, 1 per thread (gathered)
            int row = t >> 3;
            int k4  = t & 7;
            float4 x = __ldg((const float4*)(X + (size_t)endsS[row] * DDIM + kt * 32) + k4);
            As[row][k4 * 4 + 0] = x.x;
            As[row][k4 * 4 + 1] = x.y;
            As[row][k4 * 4 + 2] = x.z;
            As[row][k4 * 4 + 3] = x.w;
        }
#pragma unroll
        for (int l = 0; l < 2; l++) {   // B tile: 32 x 64 = 512 float4
            int f  = t + l * 256;
            int kk = f >> 4;
            int n4 = f & 15;
            float4 bv = __ldg((const float4*)(d_Mt + (kt * 32 + kk) * DDIM + nb * 64) + n4);
            *(float4*)&Bs[kk][n4 * 4] = bv;
        }
        __syncthreads();
#pragma unroll
        for (int kk = 0; kk < 32; kk++) {
            float a0 = As[ty * 2 + 0][kk];
            float a1 = As[ty * 2 + 1][kk];
            float4 bv = *(const float4*)&Bs[kk][tx * 4];
            acc[0][0] += a0 * bv.x; acc[0][1] += a0 * bv.y;
            acc[0][2] += a0 * bv.z; acc[0][3] += a0 * bv.w;
            acc[1][0] += a1 * bv.x; acc[1][1] += a1 * bv.y;
            acc[1][2] += a1 * bv.z; acc[1][3] += a1 * bv.w;
        }
        __syncthreads();
    }
#pragma unroll
    for (int i = 0; i < 2; i++) {
        float4 o = make_float4(acc[i][0], acc[i][1], acc[i][2], acc[i][3]);
        *(float4*)(d_V + (size_t)(rb * 32 + ty * 2 + i) * DDIM + nb * 64 + tx * 4) = o;
    }
}

// ---------------- logits: warp per token, streaming X ----------------
__global__ void logitsK(const float* __restrict__ X) {
    int token = blockIdx.x * 16 + (threadIdx.x >> 5);
    int lane  = threadIdx.x & 31;
    int s = d_seg[token];
    const float4* xr = (const float4*)X + (size_t)token * 64;
    const float4* vr = (const float4*)d_V + (size_t)s * 64;

    float4 a = __ldcs(xr + lane);
    float4 b = __ldg(vr + lane);
    float p = a.x * b.x + a.y * b.y + a.z * b.z + a.w * b.w;
    a = __ldcs(xr + lane + 32);
    b = __ldg(vr + lane + 32);
    p += a.x * b.x + a.y * b.y + a.z * b.z + a.w * b.w;

#pragma unroll
    for (int off = 16; off > 0; off >>= 1)
        p += __shfl_down_sync(0xffffffffu, p, off);
    if (lane == 0) d_logits[token] = p;
}

// ---------------- segmented softmax: block per segment over L2-hot logits ----------------
__global__ void softmaxK(float* __restrict__ out) {
    __shared__ float red[4];
    __shared__ int sStart, sLen;
    int b = blockIdx.x, t = threadIdx.x;
    int lane = t & 31, wid = t >> 5;

    if (t == 0) {
        int e  = d_ends[b];
        int st = (b == 0) ? 0 : (d_ends[b - 1] + 1);
        sStart = st; sLen = e - st + 1;
    }
    __syncthreads();
    int start = sStart, len = sLen;

    // pass 1: max
    float m = -INFINITY;
    for (int i = t; i < len; i += 128)
        m = fmaxf(m, d_logits[start + i]);
#pragma unroll
    for (int o = 16; o > 0; o >>= 1)
        m = fmaxf(m, __shfl_xor_sync(0xffffffffu, m, o));
    if (lane == 0) red[wid] = m;
    __syncthreads();
    m = fmaxf(fmaxf(red[0], red[1]), fmaxf(red[2], red[3]));

    // pass 2: sum of exp
    float s = 0.0f;
    for (int i = t; i < len; i += 128)
        s += __expf(d_logits[start + i] - m);
#pragma unroll
    for (int o = 16; o > 0; o >>= 1)
        s += __shfl_xor_sync(0xffffffffu, s, o);
    __syncthreads();
    if (lane == 0) red[wid] = s;
    __syncthreads();
    float invS = 1.0f / (red[0] + red[1] + red[2] + red[3]);

    // pass 3: write
    for (int i = t; i < len; i += 128)
        out[start + i] = __expf(d_logits[start + i] - m) * invS;
}

extern "C" void kernel_launch(void* const* d_in, const int* in_sizes, int n_in,
                              void* d_out, int out_size) {
    const float* X  = (const float*)d_in[0];
    const int*   q  = (const int*)d_in[1];
    const float* Wq = (const float*)d_in[3];
    const float* Wk = (const float*)d_in[4];
    float* out = (float*)d_out;

    initK<<<1, 256>>>();
    scanF<<<NB, 256>>>(q);
    mtK<<<DDIM, DDIM>>>(Wq, Wk);
    gemmV<<<dim3(4, 128), 256>>>(X);
    logitsK<<<NTOK / 16, 512>>>(X);
    softmaxK<<<NSEG, 128>>>(out);
}

// round 6
// speedup vs baseline: 1.1267x; 1.0312x over previous
#include <cuda_runtime.h>

#define NTOK 262144
#define NSEG 4096
#define DDIM 256
#define ADIM 128
#define NB   256      // scan blocks: NTOK / 1024

// ---------------- scratch (no allocations allowed) ----------------
__device__ int                d_seg[NTOK];
__device__ int                d_ends[NSEG];
__device__ unsigned long long d_desc[NB];     // decoupled-lookback descriptors
__device__ float              d_Mt[DDIM * DDIM];
__device__ float              d_V[NSEG * DDIM];
__device__ float              d_logits[NTOK];

// packed f32x2 helpers (Blackwell FFMA2 path)
__device__ __forceinline__ unsigned long long pack2(float lo, float hi) {
    unsigned long long r;
    asm("mov.b64 %0, {%1, %2};" : "=l"(r) : "f"(lo), "f"(hi));
    return r;
}
__device__ __forceinline__ unsigned long long fma2(unsigned long long a,
                                                   unsigned long long b,
                                                   unsigned long long c) {
    unsigned long long d;
    asm("fma.rn.f32x2 %0, %1, %2, %3;" : "=l"(d) : "l"(a), "l"(b), "l"(c));
    return d;
}
__device__ __forceinline__ void unpack2(unsigned long long v, float& lo, float& hi) {
    asm("mov.b64 {%0, %1}, %2;" : "=f"(lo), "=f"(hi) : "l"(v));
}

// ---------------- init (reset lookback flags each replay) ----------------
__global__ void initK() {
    int t = threadIdx.x;
    if (t < NB) d_desc[t] = 0ull;
}

// ---------------- single-pass scan of `queries` -> seg[] + ends[] ----------------
__global__ void scanF(const int* __restrict__ q) {
    __shared__ int warpOff[8];
    __shared__ int warpSums[8];
    __shared__ int blockAgg;
    __shared__ int blockPrefix;

    int t = threadIdx.x, b = blockIdx.x;
    int lane = t & 31, wid = t >> 5;

    int4 v = ((const int4*)q)[b * 256 + t];
    int s = v.x + v.y + v.z + v.w;

    int inc = s;
#pragma unroll
    for (int off = 1; off < 32; off <<= 1) {
        int n = __shfl_up_sync(0xffffffffu, inc, off);
        if (lane >= off) inc += n;
    }
    if (lane == 31) warpSums[wid] = inc;
    __syncthreads();

    if (wid == 0 && lane < 8) {
        int w  = warpSums[lane];
        int wi = w;
#pragma unroll
        for (int off = 1; off < 8; off <<= 1) {
            int n = __shfl_up_sync(0xffu, wi, off);
            if (lane >= off) wi += n;
        }
        warpOff[lane] = wi - w;
        if (lane == 7) {
            blockAgg = wi;
            unsigned long long pub = ((b == 0) ? (2ull << 32) : (1ull << 32))
                                     | (unsigned)wi;
            atomicExch(&d_desc[b], pub);
            if (b == 0) blockPrefix = 0;
        }
    }
    __syncthreads();

    if (b > 0 && wid == 0) {
        long long run = 0;
        int offbase = 1;
        while (true) {
            int idx = b - (offbase + lane);
            int st; unsigned val;
            if (idx >= 0) {
                unsigned long long d =
                    *((volatile const unsigned long long*)(d_desc + idx));
                st = (int)(d >> 32); val = (unsigned)d;
            } else { st = 2; val = 0; }
            unsigned ready = __ballot_sync(0xffffffffu, st != 0);
            if (ready != 0xffffffffu) continue;
            unsigned pm = __ballot_sync(0xffffffffu, st == 2);
            unsigned contrib;
            if (pm) {
                int nearest = __ffs(pm) - 1;
                contrib = (lane <= nearest) ? val : 0u;
            } else {
                contrib = val;
            }
#pragma unroll
            for (int o = 16; o > 0; o >>= 1)
                contrib += __shfl_down_sync(0xffffffffu, contrib, o);
            contrib = __shfl_sync(0xffffffffu, contrib, 0);
            run += contrib;
            if (pm) break;
            offbase += 32;
        }
        if (lane == 0) {
            blockPrefix = (int)run;
            atomicExch(&d_desc[b],
                       (2ull << 32) | (unsigned)((int)run + blockAgg));
        }
    }
    __syncthreads();

    int p  = blockPrefix + warpOff[wid] + inc - s;
    int g0 = (b * 256 + t) * 4;
    int4 sv;
    sv.x = p; if (v.x) { d_ends[p] = g0 + 0; p++; }
    sv.y = p; if (v.y) { d_ends[p] = g0 + 1; p++; }
    sv.z = p; if (v.z) { d_ends[p] = g0 + 2; p++; }
    sv.w = p; if (v.w) { d_ends[p] = g0 + 3; p++; }
    ((int4*)d_seg)[b * 256 + t] = sv;
}

// ---------------- Mt[k][n] = sum_a Wq[a][k] * Wk[a][n] ----------------
__global__ void mtK(const float* __restrict__ Wq, const float* __restrict__ Wk) {
    int k = blockIdx.x;
    int n = threadIdx.x;
    float acc = 0.0f;
#pragma unroll 8
    for (int a = 0; a < ADIM; a++)
        acc += __ldg(Wq + a * DDIM + k) * __ldg(Wk + a * DDIM + n);
    d_Mt[k * DDIM + n] = acc;
}

// ---------------- V = gather(X, ends) @ Mt ----------------
// BM=32, BN=64, BK=64; 256 threads; 2 rows x 4 cols via packed f32x2 FFMA2.
// Padded smem rows: 68 floats = 272 B (16B-aligned), conflict-free LDS/STS.128.
__global__ void gemmV(const float* __restrict__ X) {
    __shared__ __align__(16) float As[32][68];
    __shared__ __align__(16) float Bs[64][68];
    __shared__ int endsS[32];

    int t  = threadIdx.x;
    int rb = blockIdx.y;     // 0..127 (32 segments each)
    int nb = blockIdx.x;     // 0..3   (64 cols each)
    if (t < 32) endsS[t] = d_ends[rb * 32 + t];
    __syncthreads();

    int tx = t & 15;         // n: 16 x (4 cols)
    int ty = t >> 4;         // m: 16 x (2 rows)

    unsigned long long acc00 = 0, acc01 = 0, acc10 = 0, acc11 = 0;

    for (int kt = 0; kt < 4; kt++) {
        // A tile: 32 rows x 64 k = 512 float4, 2 per thread (gathered rows)
#pragma unroll
        for (int l = 0; l < 2; l++) {
            int f   = t + l * 256;
            int row = f >> 4;
            int k4  = f & 15;
            float4 x = __ldg((const float4*)(X + (size_t)endsS[row] * DDIM + kt * 64) + k4);
            *(float4*)&As[row][k4 * 4] = x;
        }
        // B tile: 64 k x 64 n = 1024 float4, 4 per thread
#pragma unroll
        for (int l = 0; l < 4; l++) {
            int f  = t + l * 256;
            int kk = f >> 4;
            int n4 = f & 15;
            float4 bv = __ldg((const float4*)(d_Mt + (size_t)(kt * 64 + kk) * DDIM + nb * 64) + n4);
            *(float4*)&Bs[kk][n4 * 4] = bv;
        }
        __syncthreads();
#pragma unroll
        for (int kk = 0; kk < 64; kk++) {
            unsigned long long A0 = pack2(As[ty * 2 + 0][kk], As[ty * 2 + 0][kk]);
            unsigned long long A1 = pack2(As[ty * 2 + 1][kk], As[ty * 2 + 1][kk]);
            const ulonglong2 bv = *(const ulonglong2*)&Bs[kk][tx * 4];
            acc00 = fma2(A0, bv.x, acc00);
            acc01 = fma2(A0, bv.y, acc01);
            acc10 = fma2(A1, bv.x, acc10);
            acc11 = fma2(A1, bv.y, acc11);
        }
        __syncthreads();
    }

    float4 o0, o1;
    unpack2(acc00, o0.x, o0.y); unpack2(acc01, o0.z, o0.w);
    unpack2(acc10, o1.x, o1.y); unpack2(acc11, o1.z, o1.w);
    *(float4*)(d_V + (size_t)(rb * 32 + ty * 2 + 0) * DDIM + nb * 64 + tx * 4) = o0;
    *(float4*)(d_V + (size_t)(rb * 32 + ty * 2 + 1) * DDIM + nb * 64 + tx * 4) = o1;
}

// ---------------- logits: warp per token, streaming X ----------------
__global__ void logitsK(const float* __restrict__ X) {
    int token = blockIdx.x * 16 + (threadIdx.x >> 5);
    int lane  = threadIdx.x & 31;
    int s = d_seg[token];
    const float4* xr = (const float4*)X + (size_t)token * 64;
    const float4* vr = (const float4*)d_V + (size_t)s * 64;

    float4 a = __ldcs(xr + lane);
    float4 b = __ldg(vr + lane);
    float p = a.x * b.x + a.y * b.y + a.z * b.z + a.w * b.w;
    a = __ldcs(xr + lane + 32);
    b = __ldg(vr + lane + 32);
    p += a.x * b.x + a.y * b.y + a.z * b.z + a.w * b.w;

#pragma unroll
    for (int off = 16; off > 0; off >>= 1)
        p += __shfl_down_sync(0xffffffffu, p, off);
    if (lane == 0) d_logits[token] = p;
}

// ---------------- segmented softmax: block per segment over L2-hot logits ----------------
__global__ void softmaxK(float* __restrict__ out) {
    __shared__ float red[4];
    __shared__ int sStart, sLen;
    int b = blockIdx.x, t = threadIdx.x;
    int lane = t & 31, wid = t >> 5;

    if (t == 0) {
        int e  = d_ends[b];
        int st = (b == 0) ? 0 : (d_ends[b - 1] + 1);
        sStart = st; sLen = e - st + 1;
    }
    __syncthreads();
    int start = sStart, len = sLen;

    float m = -INFINITY;
    for (int i = t; i < len; i += 128)
        m = fmaxf(m, d_logits[start + i]);
#pragma unroll
    for (int o = 16; o > 0; o >>= 1)
        m = fmaxf(m, __shfl_xor_sync(0xffffffffu, m, o));
    if (lane == 0) red[wid] = m;
    __syncthreads();
    m = fmaxf(fmaxf(red[0], red[1]), fmaxf(red[2], red[3]));

    float s = 0.0f;
    for (int i = t; i < len; i += 128)
        s += __expf(d_logits[start + i] - m);
#pragma unroll
    for (int o = 16; o > 0; o >>= 1)
        s += __shfl_xor_sync(0xffffffffu, s, o);
    __syncthreads();
    if (lane == 0) red[wid] = s;
    __syncthreads();
    float invS = 1.0f / (red[0] + red[1] + red[2] + red[3]);

    for (int i = t; i < len; i += 128)
        out[start + i] = __expf(d_logits[start + i] - m) * invS;
}

extern "C" void kernel_launch(void* const* d_in, const int* in_sizes, int n_in,
                              void* d_out, int out_size) {
    const float* X  = (const float*)d_in[0];
    const int*   q  = (const int*)d_in[1];
    const float* Wq = (const float*)d_in[3];
    const float* Wk = (const float*)d_in[4];
    float* out = (float*)d_out;

    initK<<<1, 256>>>();
    scanF<<<NB, 256>>>(q);
    mtK<<<DDIM, DDIM>>>(Wq, Wk);
    gemmV<<<dim3(4, 128), 256>>>(X);
    logitsK<<<NTOK / 16, 512>>>(X);
    softmaxK<<<NSEG, 128>>>(out);
}